// round 12
// baseline (speedup 1.0000x reference)
#include <cuda_runtime.h>
#include <cuda_bf16.h>
#include <cstdint>

#define TPB 384
#define GRIDX 148
#define TILE_M 192
#define BETA 3.0f
#define MAXA 5.0f

// smem: interleaved bf16 hi/lo B layouts, 16B unit = [H0,H1,L0,L1] per (ks,q)
#define B1OFF  0        // 224 rows x 64B   (value rows 0..99, loc rows 112..211)
#define B2VOFF 14336    // 56 rows x 448B
#define B2LOFF 39424    // 104 rows x 448B
#define SMEM_BYTES 86016

// pack two f32 -> bf16x2 (lo=x, hi=y) plus residual word
__device__ __forceinline__ void split_pack(float x, float y, uint32_t& H, uint32_t& L) {
    asm("cvt.rn.bf16x2.f32 %0, %1, %2;" : "=r"(H) : "f"(y), "f"(x));
    float xh = __uint_as_float(H << 16);
    float yh = __uint_as_float(H & 0xFFFF0000u);
    float xr = x - xh, yr = y - yh;
    asm("cvt.rn.bf16x2.f32 %0, %1, %2;" : "=r"(L) : "f"(yr), "f"(xr));
}
__device__ __forceinline__ void relu_split(float x, float y, uint32_t& H, uint32_t& L) {
    split_pack(fmaxf(x, 0.f), fmaxf(y, 0.f), H, L);
}

// staging: write bf16 hi at byte bH, lo at bH+8
__device__ __forceinline__ void st_split(char* sm, int bH, float v) {
    __nv_bfloat16 h = __float2bfloat16(v);
    float r = v - __bfloat162float(h);
    __nv_bfloat16 l = __float2bfloat16(r);
    *(unsigned short*)(sm + bH)     = *(unsigned short*)&h;
    *(unsigned short*)(sm + bH + 8) = *(unsigned short*)&l;
}
// interleaved byte offsets (H slot; L at +8)
__device__ __forceinline__ int b1_byte(int row, int k) {
    int w = k >> 1;
    return row * 64 + (w & 3) * 16 + ((w >> 2) << 2) + ((k & 1) << 1);
}
__device__ __forceinline__ int b2_byte(int row, int k) {
    int w = k >> 1;
    return row * 448 + (w >> 3) * 64 + ((w & 3) << 4) + (((w >> 2) & 1) << 2) + ((k & 1) << 1);
}

// VOLATILE on purpose: prevents ptxas from hoisting/pipelining MMAs, which
// explodes live ranges and spills (R7/R8/R9 regressions all traced to
// non-volatile here). Do not remove volatile. ILP is created in SOURCE order
// instead (term-major chunked issue below).
__device__ __forceinline__ void mma16816(float* c, const uint32_t* a, uint32_t b0, uint32_t b1) {
    asm volatile(
        "mma.sync.aligned.m16n8k16.row.col.f32.bf16.bf16.f32 "
        "{%0,%1,%2,%3}, {%4,%5,%6,%7}, {%8,%9}, {%0,%1,%2,%3};"
        : "+f"(c[0]), "+f"(c[1]), "+f"(c[2]), "+f"(c[3])
        : "r"(a[0]), "r"(a[1]), "r"(a[2]), "r"(a[3]), "r"(b0), "r"(b1));
}

__device__ __forceinline__ float fast_tanh(float x) {
    float e = __expf(2.0f * x);
    return 1.0f - __fdividef(2.0f, e + 1.0f);
}

__global__ __launch_bounds__(TPB, 1)
void net_kernel(const float* __restrict__ s,  const float* __restrict__ a,
                const float* __restrict__ wv1, const float* __restrict__ bv1,
                const float* __restrict__ wv2, const float* __restrict__ bv2,
                const float* __restrict__ wl1, const float* __restrict__ bl1,
                const float* __restrict__ wl2, const float* __restrict__ bl2,
                float* __restrict__ out, int nrows)
{
    extern __shared__ __align__(16) char sm[];
    const int tid  = threadIdx.x;
    const int w    = tid >> 5;
    const int lane = tid & 31;
    const int g    = lane >> 2;
    const int q    = lane & 3;

    // zero all smem (covers every pad row/col)
    for (int i = tid * 16; i < SMEM_BYTES; i += TPB * 16)
        *(float4*)(sm + i) = make_float4(0.f, 0.f, 0.f, 0.f);
    __syncthreads();

    // ---- stage weights ----
    // B1: value rows 0..99, loc rows 112..211; k<10 = w1[k][n], k=10 = bias
    for (int i = tid; i < 2200; i += TPB) {
        int tower = i / 1100, rem = i % 1100, n = rem / 11, k = rem % 11;
        float v = (k < 10) ? (tower ? wl1[k * 100 + n] : wv1[k * 100 + n])
                           : (tower ? bl1[n] : bv1[n]);
        st_split(sm, B1OFF + b1_byte(tower ? 112 + n : n, k), v);
    }
    // B2v: permuted rows sigma(c); k<100 = wv2[k][sig], k=100 = bias
    for (int i = tid; i < 56 * 101; i += TPB) {
        int c = i / 101, k = i % 101;
        int sig = (c % 8) / 2 + 8 * (c / 8) + 4 * (c % 2);
        if (sig < 50)
            st_split(sm, B2VOFF + b2_byte(c, k), (k < 100) ? wv2[k * 50 + sig] : bv2[sig]);
    }
    // B2l: row c = 2n+comp
    for (int i = tid; i < 100 * 101; i += TPB) {
        int c = i / 101, k = i % 101;
        float v = (k < 100) ? wl2[(c >> 1) * 200 + k * 2 + (c & 1)] : bl2[c];
        st_split(sm, B2LOFF + b2_byte(c, k), v);
    }
    __syncthreads();

    const int ntiles = (nrows + TILE_M - 1) / TILE_M;
    const int lr0 = w * 16 + g;

    // loop-invariant base pointers; all LDS offsets below are compile-time immediates
    const char* pB1 = sm + g * 64  + q * 16;   // B1: + j*512 (+ 112*64 for loc tower)
    const char* pB2 = sm + g * 448 + q * 16;   // B2: + B2xOFF + j*3584 + ks*64

    for (int tile = blockIdx.x; tile < ntiles; tile += GRIDX) {
        const int grow0 = tile * TILE_M + lr0;
        const int grow1 = grow0 + 8;

        // ---- GEMM1 A-fragments from global s (K=16: s cols 0..9, bias at 10) ----
        uint32_t saH[4], saL[4];
        {
            float2 p0 = make_float2(0.f, 0.f), p1 = p0, e0 = p0, e1 = p0;
            if (grow0 < nrows) p0 = *(const float2*)(s + (size_t)grow0 * 10 + 2 * q);
            if (grow1 < nrows) p1 = *(const float2*)(s + (size_t)grow1 * 10 + 2 * q);
            if (q == 0) {
                if (grow0 < nrows) e0 = *(const float2*)(s + (size_t)grow0 * 10 + 8);
                if (grow1 < nrows) e1 = *(const float2*)(s + (size_t)grow1 * 10 + 8);
            } else if (q == 1) {
                e0.x = 1.0f; e1.x = 1.0f;
            }
            split_pack(p0.x, p0.y, saH[0], saL[0]);
            split_pack(p1.x, p1.y, saH[1], saL[1]);
            split_pack(e0.x, e0.y, saH[2], saL[2]);
            split_pack(e1.x, e1.y, saH[3], saL[3]);
        }
        float2 av0 = make_float2(0.f, 0.f), av1 = av0;
        if (grow0 < nrows) av0 = ((const float2*)a)[grow0];
        if (grow1 < nrows) av1 = ((const float2*)a)[grow1];

        // ================= GEMM1v: term-major in chunks {4,4,5} =================
        float dv[13][4];
        #pragma unroll
        for (int j = 0; j < 13; j++) { dv[j][0]=0.f; dv[j][1]=0.f; dv[j][2]=0.f; dv[j][3]=0.f; }
        {
            const int c0[3] = {0, 4, 8}, c1[3] = {4, 8, 13};
            #pragma unroll
            for (int c = 0; c < 3; c++) {
                uint4 bb[5];
                #pragma unroll
                for (int jj = 0; jj < 5; jj++)
                    if (c0[c] + jj < c1[c]) bb[jj] = *(const uint4*)(pB1 + (c0[c] + jj) * 512);
                #pragma unroll
                for (int jj = 0; jj < 5; jj++)
                    if (c0[c] + jj < c1[c]) mma16816(dv[c0[c] + jj], saH, bb[jj].x, bb[jj].y);
                #pragma unroll
                for (int jj = 0; jj < 5; jj++)
                    if (c0[c] + jj < c1[c]) mma16816(dv[c0[c] + jj], saH, bb[jj].z, bb[jj].w);
                #pragma unroll
                for (int jj = 0; jj < 5; jj++)
                    if (c0[c] + jj < c1[c]) mma16816(dv[c0[c] + jj], saL, bb[jj].x, bb[jj].y);
            }
        }
        // relu + split: D-frag -> A-frag (registers only); dv dies here
        uint32_t vaH[7][4], vaL[7][4];
        #pragma unroll
        for (int ks = 0; ks < 6; ks++) {
            relu_split(dv[2*ks][0],   dv[2*ks][1],   vaH[ks][0], vaL[ks][0]);
            relu_split(dv[2*ks][2],   dv[2*ks][3],   vaH[ks][1], vaL[ks][1]);
            relu_split(dv[2*ks+1][0], dv[2*ks+1][1], vaH[ks][2], vaL[ks][2]);
            relu_split(dv[2*ks+1][2], dv[2*ks+1][3], vaH[ks][3], vaL[ks][3]);
        }
        relu_split(dv[12][0], dv[12][1], vaH[6][0], vaL[6][0]);
        relu_split(dv[12][2], dv[12][3], vaH[6][1], vaL[6][1]);
        if (q == 2) { vaH[6][0] = 0x3F80u; vaL[6][0] = 0u; vaH[6][1] = 0x3F80u; vaL[6][1] = 0u; }
        vaH[6][2] = 0u; vaH[6][3] = 0u; vaL[6][2] = 0u; vaL[6][3] = 0u;

        // ================= GEMM2v: term-major, bb[7] register-cached =================
        float cv[7][4];
        #pragma unroll
        for (int j = 0; j < 7; j++) { cv[j][0]=0.f; cv[j][1]=0.f; cv[j][2]=0.f; cv[j][3]=0.f; }
        #pragma unroll
        for (int ks = 0; ks < 7; ks++) {
            uint4 bb[7];
            #pragma unroll
            for (int j = 0; j < 7; j++) bb[j] = *(const uint4*)(pB2 + B2VOFF + j * 3584 + ks * 64);
            #pragma unroll
            for (int j = 0; j < 7; j++) mma16816(cv[j], vaH[ks], bb[j].x, bb[j].y);
            #pragma unroll
            for (int j = 0; j < 7; j++) mma16816(cv[j], vaH[ks], bb[j].z, bb[j].w);
            #pragma unroll
            for (int j = 0; j < 7; j++) mma16816(cv[j], vaL[ks], bb[j].x, bb[j].y);
        }

        // ================= GEMM1l: term-major in chunks {4,4,5} =================
        float dl[13][4];
        #pragma unroll
        for (int j = 0; j < 13; j++) { dl[j][0]=0.f; dl[j][1]=0.f; dl[j][2]=0.f; dl[j][3]=0.f; }
        {
            const int c0[3] = {0, 4, 8}, c1[3] = {4, 8, 13};
            #pragma unroll
            for (int c = 0; c < 3; c++) {
                uint4 bb[5];
                #pragma unroll
                for (int jj = 0; jj < 5; jj++)
                    if (c0[c] + jj < c1[c]) bb[jj] = *(const uint4*)(pB1 + 112 * 64 + (c0[c] + jj) * 512);
                #pragma unroll
                for (int jj = 0; jj < 5; jj++)
                    if (c0[c] + jj < c1[c]) mma16816(dl[c0[c] + jj], saH, bb[jj].x, bb[jj].y);
                #pragma unroll
                for (int jj = 0; jj < 5; jj++)
                    if (c0[c] + jj < c1[c]) mma16816(dl[c0[c] + jj], saH, bb[jj].z, bb[jj].w);
                #pragma unroll
                for (int jj = 0; jj < 5; jj++)
                    if (c0[c] + jj < c1[c]) mma16816(dl[c0[c] + jj], saL, bb[jj].x, bb[jj].y);
            }
        }
        uint32_t laH[7][4], laL[7][4];
        #pragma unroll
        for (int ks = 0; ks < 6; ks++) {
            relu_split(dl[2*ks][0],   dl[2*ks][1],   laH[ks][0], laL[ks][0]);
            relu_split(dl[2*ks][2],   dl[2*ks][3],   laH[ks][1], laL[ks][1]);
            relu_split(dl[2*ks+1][0], dl[2*ks+1][1], laH[ks][2], laL[ks][2]);
            relu_split(dl[2*ks+1][2], dl[2*ks+1][3], laH[ks][3], laL[ks][3]);
        }
        relu_split(dl[12][0], dl[12][1], laH[6][0], laL[6][0]);
        relu_split(dl[12][2], dl[12][3], laH[6][1], laL[6][1]);
        if (q == 2) { laH[6][0] = 0x3F80u; laL[6][0] = 0u; laH[6][1] = 0x3F80u; laL[6][1] = 0u; }
        laH[6][2] = 0u; laH[6][3] = 0u; laL[6][2] = 0u; laL[6][3] = 0u;

        // ===== GEMM2l: two j-halves {7,6}, term-major, epilogue fused per half =====
        float ws0 = 0.f, vs0 = 0.f, ws1 = 0.f, vs1 = 0.f;
        #pragma unroll
        for (int hf = 0; hf < 2; hf++) {
            const int j0 = hf ? 7 : 0;
            const int nj = hf ? 6 : 7;
            float lc[7][4];
            #pragma unroll
            for (int j = 0; j < 7; j++) { lc[j][0]=0.f; lc[j][1]=0.f; lc[j][2]=0.f; lc[j][3]=0.f; }
            #pragma unroll
            for (int ks = 0; ks < 7; ks++) {
                uint4 bb[7];
                #pragma unroll
                for (int j = 0; j < 7; j++)
                    if (j < nj) bb[j] = *(const uint4*)(pB2 + B2LOFF + (j0 + j) * 3584 + ks * 64);
                #pragma unroll
                for (int j = 0; j < 7; j++)
                    if (j < nj) mma16816(lc[j], laH[ks], bb[j].x, bb[j].y);
                #pragma unroll
                for (int j = 0; j < 7; j++)
                    if (j < nj) mma16816(lc[j], laH[ks], bb[j].z, bb[j].w);
                #pragma unroll
                for (int j = 0; j < 7; j++)
                    if (j < nj) mma16816(lc[j], laL[ks], bb[j].x, bb[j].y);
            }
            // fused epilogue for this half: centroid n = 4*(j0+j)+q
            #pragma unroll
            for (int j = 0; j < 7; j++) {
                if (j < nj) {
                    const int jj = j0 + j;
                    const bool valid = (4 * jj + q) < 50;
                    {
                        float tx = MAXA * fast_tanh(lc[j][0]) - av0.x;
                        float ty = MAXA * fast_tanh(lc[j][1]) - av0.y;
                        float e = valid ? __expf(-BETA * sqrtf(tx * tx + ty * ty)) : 0.f;
                        float c = (jj & 1) ? cv[jj >> 1][1] : cv[jj >> 1][0];
                        ws0 += e; vs0 += e * c;
                    }
                    {
                        float tx = MAXA * fast_tanh(lc[j][2]) - av1.x;
                        float ty = MAXA * fast_tanh(lc[j][3]) - av1.y;
                        float e = valid ? __expf(-BETA * sqrtf(tx * tx + ty * ty)) : 0.f;
                        float c = (jj & 1) ? cv[jj >> 1][3] : cv[jj >> 1][2];
                        ws1 += e; vs1 += e * c;
                    }
                }
            }
        }

        ws0 += __shfl_xor_sync(0xffffffffu, ws0, 1);
        vs0 += __shfl_xor_sync(0xffffffffu, vs0, 1);
        ws1 += __shfl_xor_sync(0xffffffffu, ws1, 1);
        vs1 += __shfl_xor_sync(0xffffffffu, vs1, 1);
        ws0 += __shfl_xor_sync(0xffffffffu, ws0, 2);
        vs0 += __shfl_xor_sync(0xffffffffu, vs0, 2);
        ws1 += __shfl_xor_sync(0xffffffffu, ws1, 2);
        vs1 += __shfl_xor_sync(0xffffffffu, vs1, 2);
        if (q == 0) {
            if (grow0 < nrows) out[grow0] = vs0 / ws0;
            if (grow1 < nrows) out[grow1] = vs1 / ws1;
        }
    }
}

extern "C" void kernel_launch(void* const* d_in, const int* in_sizes, int n_in,
                              void* d_out, int out_size)
{
    const float* s   = (const float*)d_in[0];
    const float* a   = (const float*)d_in[1];
    const float* wv1 = (const float*)d_in[2];
    const float* bv1 = (const float*)d_in[3];
    const float* wv2 = (const float*)d_in[4];
    const float* bv2 = (const float*)d_in[5];
    const float* wl1 = (const float*)d_in[6];
    const float* bl1 = (const float*)d_in[7];
    const float* wl2 = (const float*)d_in[8];
    const float* bl2 = (const float*)d_in[9];
    float* out = (float*)d_out;

    int nrows = in_sizes[0] / 10;

    cudaFuncSetAttribute(net_kernel, cudaFuncAttributeMaxDynamicSharedMemorySize, SMEM_BYTES);
    net_kernel<<<GRIDX, TPB, SMEM_BYTES>>>(s, a, wv1, bv1, wv2, bv2,
                                           wl1, bl1, wl2, bl2, out, nrows);
}

// round 13
// speedup vs baseline: 1.0735x; 1.0735x over previous
#include <cuda_runtime.h>
#include <cuda_bf16.h>
#include <cstdint>

#define TPB 384
#define GRIDX 148
#define TILE_M 192
#define BETA 3.0f
#define MAXA 5.0f

// smem: interleaved bf16 hi/lo B layouts, 16B unit = [H0,H1,L0,L1] per (ks,q)
#define B1OFF  0        // 224 rows x 64B   (value rows 0..99, loc rows 112..211)
#define B2VOFF 14336    // 56 rows x 448B
#define B2LOFF 39424    // 104 rows x 448B
#define SMEM_BYTES 86016

// pack two f32 -> bf16x2 (lo=x, hi=y) plus residual word
__device__ __forceinline__ void split_pack(float x, float y, uint32_t& H, uint32_t& L) {
    asm("cvt.rn.bf16x2.f32 %0, %1, %2;" : "=r"(H) : "f"(y), "f"(x));
    float xh = __uint_as_float(H << 16);
    float yh = __uint_as_float(H & 0xFFFF0000u);
    float xr = x - xh, yr = y - yh;
    asm("cvt.rn.bf16x2.f32 %0, %1, %2;" : "=r"(L) : "f"(yr), "f"(xr));
}
__device__ __forceinline__ void relu_split(float x, float y, uint32_t& H, uint32_t& L) {
    split_pack(fmaxf(x, 0.f), fmaxf(y, 0.f), H, L);
}

// staging: write bf16 hi at byte bH, lo at bH+8
__device__ __forceinline__ void st_split(char* sm, int bH, float v) {
    __nv_bfloat16 h = __float2bfloat16(v);
    float r = v - __bfloat162float(h);
    __nv_bfloat16 l = __float2bfloat16(r);
    *(unsigned short*)(sm + bH)     = *(unsigned short*)&h;
    *(unsigned short*)(sm + bH + 8) = *(unsigned short*)&l;
}
// interleaved byte offsets (H slot; L at +8)
__device__ __forceinline__ int b1_byte(int row, int k) {
    int w = k >> 1;
    return row * 64 + (w & 3) * 16 + ((w >> 2) << 2) + ((k & 1) << 1);
}
__device__ __forceinline__ int b2_byte(int row, int k) {
    int w = k >> 1;
    return row * 448 + (w >> 3) * 64 + ((w & 3) << 4) + (((w >> 2) & 1) << 2) + ((k & 1) << 1);
}

// VOLATILE on purpose: prevents ptxas from hoisting/pipelining MMAs, which
// explodes live ranges and spills (R7/R8/R9 regressions all traced to
// non-volatile here). Do not remove volatile.
__device__ __forceinline__ void mma16816(float* c, const uint32_t* a, uint32_t b0, uint32_t b1) {
    asm volatile(
        "mma.sync.aligned.m16n8k16.row.col.f32.bf16.bf16.f32 "
        "{%0,%1,%2,%3}, {%4,%5,%6,%7}, {%8,%9}, {%0,%1,%2,%3};"
        : "+f"(c[0]), "+f"(c[1]), "+f"(c[2]), "+f"(c[3])
        : "r"(a[0]), "r"(a[1]), "r"(a[2]), "r"(a[3]), "r"(b0), "r"(b1));
}

__device__ __forceinline__ float fast_tanh(float x) {
    float e = __expf(2.0f * x);
    return 1.0f - __fdividef(2.0f, e + 1.0f);
}

__global__ __launch_bounds__(TPB, 1)
void net_kernel(const float* __restrict__ s,  const float* __restrict__ a,
                const float* __restrict__ wv1, const float* __restrict__ bv1,
                const float* __restrict__ wv2, const float* __restrict__ bv2,
                const float* __restrict__ wl1, const float* __restrict__ bl1,
                const float* __restrict__ wl2, const float* __restrict__ bl2,
                float* __restrict__ out, int nrows)
{
    extern __shared__ __align__(16) char sm[];
    const int tid  = threadIdx.x;
    const int w    = tid >> 5;
    const int lane = tid & 31;
    const int g    = lane >> 2;
    const int q    = lane & 3;

    // zero all smem (covers every pad row/col)
    for (int i = tid * 16; i < SMEM_BYTES; i += TPB * 16)
        *(float4*)(sm + i) = make_float4(0.f, 0.f, 0.f, 0.f);
    __syncthreads();

    // ---- stage weights ----
    // B1: value rows 0..99, loc rows 112..211; k<10 = w1[k][n], k=10 = bias
    for (int i = tid; i < 2200; i += TPB) {
        int tower = i / 1100, rem = i % 1100, n = rem / 11, k = rem % 11;
        float v = (k < 10) ? (tower ? wl1[k * 100 + n] : wv1[k * 100 + n])
                           : (tower ? bl1[n] : bv1[n]);
        st_split(sm, B1OFF + b1_byte(tower ? 112 + n : n, k), v);
    }
    // B2v: permuted rows sigma(c); k<100 = wv2[k][sig], k=100 = bias
    for (int i = tid; i < 56 * 101; i += TPB) {
        int c = i / 101, k = i % 101;
        int sig = (c % 8) / 2 + 8 * (c / 8) + 4 * (c % 2);
        if (sig < 50)
            st_split(sm, B2VOFF + b2_byte(c, k), (k < 100) ? wv2[k * 50 + sig] : bv2[sig]);
    }
    // B2l: row c = 2n+comp
    for (int i = tid; i < 100 * 101; i += TPB) {
        int c = i / 101, k = i % 101;
        float v = (k < 100) ? wl2[(c >> 1) * 200 + k * 2 + (c & 1)] : bl2[c];
        st_split(sm, B2LOFF + b2_byte(c, k), v);
    }
    __syncthreads();

    const int ntiles = (nrows + TILE_M - 1) / TILE_M;
    const int lr0 = w * 16 + g;

    // loop-invariant base pointers; all LDS offsets below are compile-time immediates
    const char* pB1 = sm + g * 64  + q * 16;   // B1: + j*512 (+ 112*64 for loc tower)
    const char* pB2 = sm + g * 448 + q * 16;   // B2: + B2xOFF + j*3584 + ks*64

    // ---- software-pipelined global loads: prefetch for first tile ----
    float2 pf_p0, pf_p1, pf_e0, pf_e1, pf_a0, pf_a1;
    {
        const int t0 = blockIdx.x;
        const int r0 = t0 * TILE_M + lr0, r1 = r0 + 8;
        pf_p0 = make_float2(0.f, 0.f); pf_p1 = pf_p0; pf_e0 = pf_p0; pf_e1 = pf_p0;
        pf_a0 = pf_p0; pf_a1 = pf_p0;
        if (t0 < ntiles) {
            if (r0 < nrows) { pf_p0 = *(const float2*)(s + (size_t)r0 * 10 + 2 * q);
                              pf_a0 = ((const float2*)a)[r0]; }
            if (r1 < nrows) { pf_p1 = *(const float2*)(s + (size_t)r1 * 10 + 2 * q);
                              pf_a1 = ((const float2*)a)[r1]; }
            if (q == 0) {
                if (r0 < nrows) pf_e0 = *(const float2*)(s + (size_t)r0 * 10 + 8);
                if (r1 < nrows) pf_e1 = *(const float2*)(s + (size_t)r1 * 10 + 8);
            }
        }
    }

    for (int tile = blockIdx.x; tile < ntiles; tile += GRIDX) {
        const int grow0 = tile * TILE_M + lr0;
        const int grow1 = grow0 + 8;

        // ---- consume prefetched rows into GEMM1 A-fragments ----
        uint32_t saH[4], saL[4];
        {
            float2 e0 = pf_e0, e1 = pf_e1;
            if (q == 1) { e0 = make_float2(1.f, 0.f); e1 = make_float2(1.f, 0.f); }
            split_pack(pf_p0.x, pf_p0.y, saH[0], saL[0]);
            split_pack(pf_p1.x, pf_p1.y, saH[1], saL[1]);
            split_pack(e0.x, e0.y, saH[2], saL[2]);
            split_pack(e1.x, e1.y, saH[3], saL[3]);
        }
        const float2 av0 = pf_a0, av1 = pf_a1;

        // ---- issue next tile's loads now; body below covers the latency ----
        {
            const int nt = tile + GRIDX;
            if (nt < ntiles) {
                const int r0 = nt * TILE_M + lr0, r1 = r0 + 8;
                pf_p0 = make_float2(0.f, 0.f); pf_p1 = pf_p0; pf_e0 = pf_p0; pf_e1 = pf_p0;
                pf_a0 = pf_p0; pf_a1 = pf_p0;
                if (r0 < nrows) { pf_p0 = *(const float2*)(s + (size_t)r0 * 10 + 2 * q);
                                  pf_a0 = ((const float2*)a)[r0]; }
                if (r1 < nrows) { pf_p1 = *(const float2*)(s + (size_t)r1 * 10 + 2 * q);
                                  pf_a1 = ((const float2*)a)[r1]; }
                if (q == 0) {
                    if (r0 < nrows) pf_e0 = *(const float2*)(s + (size_t)r0 * 10 + 8);
                    if (r1 < nrows) pf_e1 = *(const float2*)(s + (size_t)r1 * 10 + 8);
                }
            }
        }

        // ================= VALUE tower =================
        float dv[13][4];
        #pragma unroll
        for (int j = 0; j < 13; j++) { dv[j][0]=0.f; dv[j][1]=0.f; dv[j][2]=0.f; dv[j][3]=0.f; }
        #pragma unroll
        for (int j = 0; j < 13; j++) {
            uint4 bb = *(const uint4*)(pB1 + j * 512);
            mma16816(dv[j], saH, bb.x, bb.y);
            mma16816(dv[j], saH, bb.z, bb.w);
            mma16816(dv[j], saL, bb.x, bb.y);
        }
        // relu + split: D-frag -> A-frag (registers only); dv dies here
        uint32_t vaH[7][4], vaL[7][4];
        #pragma unroll
        for (int ks = 0; ks < 6; ks++) {
            relu_split(dv[2*ks][0],   dv[2*ks][1],   vaH[ks][0], vaL[ks][0]);
            relu_split(dv[2*ks][2],   dv[2*ks][3],   vaH[ks][1], vaL[ks][1]);
            relu_split(dv[2*ks+1][0], dv[2*ks+1][1], vaH[ks][2], vaL[ks][2]);
            relu_split(dv[2*ks+1][2], dv[2*ks+1][3], vaH[ks][3], vaL[ks][3]);
        }
        relu_split(dv[12][0], dv[12][1], vaH[6][0], vaL[6][0]);
        relu_split(dv[12][2], dv[12][3], vaH[6][1], vaL[6][1]);
        if (q == 2) { vaH[6][0] = 0x3F80u; vaL[6][0] = 0u; vaH[6][1] = 0x3F80u; vaL[6][1] = 0u; }
        vaH[6][2] = 0u; vaH[6][3] = 0u; vaL[6][2] = 0u; vaL[6][3] = 0u;

        // GEMM2v: cv = hv x B2v^T
        float cv[7][4];
        #pragma unroll
        for (int j = 0; j < 7; j++) { cv[j][0]=0.f; cv[j][1]=0.f; cv[j][2]=0.f; cv[j][3]=0.f; }
        #pragma unroll
        for (int ks = 0; ks < 7; ks++) {
            #pragma unroll
            for (int j = 0; j < 7; j++) {
                uint4 bb = *(const uint4*)(pB2 + B2VOFF + j * 3584 + ks * 64);
                mma16816(cv[j], vaH[ks], bb.x, bb.y);
                mma16816(cv[j], vaH[ks], bb.z, bb.w);
                mma16816(cv[j], vaL[ks], bb.x, bb.y);
            }
        }

        // ================= LOC tower =================
        float dl[13][4];
        #pragma unroll
        for (int j = 0; j < 13; j++) { dl[j][0]=0.f; dl[j][1]=0.f; dl[j][2]=0.f; dl[j][3]=0.f; }
        #pragma unroll
        for (int j = 0; j < 13; j++) {
            uint4 bb = *(const uint4*)(pB1 + 112 * 64 + j * 512);
            mma16816(dl[j], saH, bb.x, bb.y);
            mma16816(dl[j], saH, bb.z, bb.w);
            mma16816(dl[j], saL, bb.x, bb.y);
        }
        uint32_t laH[7][4], laL[7][4];
        #pragma unroll
        for (int ks = 0; ks < 6; ks++) {
            relu_split(dl[2*ks][0],   dl[2*ks][1],   laH[ks][0], laL[ks][0]);
            relu_split(dl[2*ks][2],   dl[2*ks][3],   laH[ks][1], laL[ks][1]);
            relu_split(dl[2*ks+1][0], dl[2*ks+1][1], laH[ks][2], laL[ks][2]);
            relu_split(dl[2*ks+1][2], dl[2*ks+1][3], laH[ks][3], laL[ks][3]);
        }
        relu_split(dl[12][0], dl[12][1], laH[6][0], laL[6][0]);
        relu_split(dl[12][2], dl[12][3], laH[6][1], laL[6][1]);
        if (q == 2) { laH[6][0] = 0x3F80u; laL[6][0] = 0u; laH[6][1] = 0x3F80u; laL[6][1] = 0u; }
        laH[6][2] = 0u; laH[6][3] = 0u; laL[6][2] = 0u; laL[6][3] = 0u;

        // GEMM2l: locpre = hl x B2l^T
        float lc[13][4];
        #pragma unroll
        for (int j = 0; j < 13; j++) { lc[j][0]=0.f; lc[j][1]=0.f; lc[j][2]=0.f; lc[j][3]=0.f; }
        #pragma unroll
        for (int ks = 0; ks < 7; ks++) {
            #pragma unroll
            for (int j = 0; j < 13; j++) {
                uint4 bb = *(const uint4*)(pB2 + B2LOFF + j * 3584 + ks * 64);
                mma16816(lc[j], laH[ks], bb.x, bb.y);
                mma16816(lc[j], laH[ks], bb.z, bb.w);
                mma16816(lc[j], laL[ks], bb.x, bb.y);
            }
        }

        // ================= epilogue =================
        // tile j, thread q: centroid n = 4j+q; cols (2q,2q+1) = (x,y); rows g and g+8
        float ws0 = 0.f, vs0 = 0.f, ws1 = 0.f, vs1 = 0.f;
        #pragma unroll
        for (int j = 0; j < 13; j++) {
            const bool valid = (4 * j + q) < 50;
            {
                float tx = MAXA * fast_tanh(lc[j][0]) - av0.x;
                float ty = MAXA * fast_tanh(lc[j][1]) - av0.y;
                float d2 = tx * tx + ty * ty;
                float dist = d2 * rsqrtf(d2 + 1e-30f);
                float e = valid ? __expf(-BETA * dist) : 0.f;
                float c = (j & 1) ? cv[j >> 1][1] : cv[j >> 1][0];
                ws0 += e; vs0 += e * c;
            }
            {
                float tx = MAXA * fast_tanh(lc[j][2]) - av1.x;
                float ty = MAXA * fast_tanh(lc[j][3]) - av1.y;
                float d2 = tx * tx + ty * ty;
                float dist = d2 * rsqrtf(d2 + 1e-30f);
                float e = valid ? __expf(-BETA * dist) : 0.f;
                float c = (j & 1) ? cv[j >> 1][3] : cv[j >> 1][2];
                ws1 += e; vs1 += e * c;
            }
        }
        ws0 += __shfl_xor_sync(0xffffffffu, ws0, 1);
        vs0 += __shfl_xor_sync(0xffffffffu, vs0, 1);
        ws1 += __shfl_xor_sync(0xffffffffu, ws1, 1);
        vs1 += __shfl_xor_sync(0xffffffffu, vs1, 1);
        ws0 += __shfl_xor_sync(0xffffffffu, ws0, 2);
        vs0 += __shfl_xor_sync(0xffffffffu, vs0, 2);
        ws1 += __shfl_xor_sync(0xffffffffu, ws1, 2);
        vs1 += __shfl_xor_sync(0xffffffffu, vs1, 2);
        if (q == 0) {
            if (grow0 < nrows) out[grow0] = vs0 / ws0;
            if (grow1 < nrows) out[grow1] = vs1 / ws1;
        }
    }
}

extern "C" void kernel_launch(void* const* d_in, const int* in_sizes, int n_in,
                              void* d_out, int out_size)
{
    const float* s   = (const float*)d_in[0];
    const float* a   = (const float*)d_in[1];
    const float* wv1 = (const float*)d_in[2];
    const float* bv1 = (const float*)d_in[3];
    const float* wv2 = (const float*)d_in[4];
    const float* bv2 = (const float*)d_in[5];
    const float* wl1 = (const float*)d_in[6];
    const float* bl1 = (const float*)d_in[7];
    const float* wl2 = (const float*)d_in[8];
    const float* bl2 = (const float*)d_in[9];
    float* out = (float*)d_out;

    int nrows = in_sizes[0] / 10;

    cudaFuncSetAttribute(net_kernel, cudaFuncAttributeMaxDynamicSharedMemorySize, SMEM_BYTES);
    net_kernel<<<GRIDX, TPB, SMEM_BYTES>>>(s, a, wv1, bv1, wv2, bv2,
                                           wl1, bl1, wl2, bl2, out, nrows);
}

// round 14
// speedup vs baseline: 1.0814x; 1.0074x over previous
#include <cuda_runtime.h>
#include <cuda_bf16.h>
#include <cstdint>

#define TPB 512
#define GRIDX 148
#define TILE_M 256
#define BETA 3.0f
#define MAXA 5.0f

// smem: interleaved bf16 hi/lo B layouts, 16B unit = [H0,H1,L0,L1] per (ks,q)
#define B1OFF  0        // 224 rows x 64B   (value rows 0..99, loc rows 112..211)
#define B2VOFF 14336    // 56 rows x 448B
#define B2LOFF 39424    // 104 rows x 448B
#define SMEM_BYTES 86016

// pack two f32 -> bf16x2 (lo=x, hi=y) plus residual word
__device__ __forceinline__ void split_pack(float x, float y, uint32_t& H, uint32_t& L) {
    asm("cvt.rn.bf16x2.f32 %0, %1, %2;" : "=r"(H) : "f"(y), "f"(x));
    float xh = __uint_as_float(H << 16);
    float yh = __uint_as_float(H & 0xFFFF0000u);
    float xr = x - xh, yr = y - yh;
    asm("cvt.rn.bf16x2.f32 %0, %1, %2;" : "=r"(L) : "f"(yr), "f"(xr));
}
__device__ __forceinline__ void relu_split(float x, float y, uint32_t& H, uint32_t& L) {
    split_pack(fmaxf(x, 0.f), fmaxf(y, 0.f), H, L);
}

// staging: write bf16 hi at byte bH, lo at bH+8
__device__ __forceinline__ void st_split(char* sm, int bH, float v) {
    __nv_bfloat16 h = __float2bfloat16(v);
    float r = v - __bfloat162float(h);
    __nv_bfloat16 l = __float2bfloat16(r);
    *(unsigned short*)(sm + bH)     = *(unsigned short*)&h;
    *(unsigned short*)(sm + bH + 8) = *(unsigned short*)&l;
}
// interleaved byte offsets (H slot; L at +8)
__device__ __forceinline__ int b1_byte(int row, int k) {
    int w = k >> 1;
    return row * 64 + (w & 3) * 16 + ((w >> 2) << 2) + ((k & 1) << 1);
}
__device__ __forceinline__ int b2_byte(int row, int k) {
    int w = k >> 1;
    return row * 448 + (w >> 3) * 64 + ((w & 3) << 4) + (((w >> 2) & 1) << 2) + ((k & 1) << 1);
}

// VOLATILE on purpose: prevents ptxas from hoisting/pipelining MMAs, which
// explodes live ranges and spills (R7/R8/R9 regressions all traced to
// non-volatile here). Do not remove volatile.
__device__ __forceinline__ void mma16816(float* c, const uint32_t* a, uint32_t b0, uint32_t b1) {
    asm volatile(
        "mma.sync.aligned.m16n8k16.row.col.f32.bf16.bf16.f32 "
        "{%0,%1,%2,%3}, {%4,%5,%6,%7}, {%8,%9}, {%0,%1,%2,%3};"
        : "+f"(c[0]), "+f"(c[1]), "+f"(c[2]), "+f"(c[3])
        : "r"(a[0]), "r"(a[1]), "r"(a[2]), "r"(a[3]), "r"(b0), "r"(b1));
}

__device__ __forceinline__ float fast_tanh(float x) {
    float e = __expf(2.0f * x);
    return 1.0f - __fdividef(2.0f, e + 1.0f);
}

__global__ __launch_bounds__(TPB, 1)
void net_kernel(const float* __restrict__ s,  const float* __restrict__ a,
                const float* __restrict__ wv1, const float* __restrict__ bv1,
                const float* __restrict__ wv2, const float* __restrict__ bv2,
                const float* __restrict__ wl1, const float* __restrict__ bl1,
                const float* __restrict__ wl2, const float* __restrict__ bl2,
                float* __restrict__ out, int nrows)
{
    extern __shared__ __align__(16) char sm[];
    const int tid  = threadIdx.x;
    const int w    = tid >> 5;
    const int lane = tid & 31;
    const int g    = lane >> 2;
    const int q    = lane & 3;

    // zero all smem (covers every pad row/col)
    for (int i = tid * 16; i < SMEM_BYTES; i += TPB * 16)
        *(float4*)(sm + i) = make_float4(0.f, 0.f, 0.f, 0.f);
    __syncthreads();

    // ---- stage weights ----
    // B1: value rows 0..99, loc rows 112..211; k<10 = w1[k][n], k=10 = bias
    for (int i = tid; i < 2200; i += TPB) {
        int tower = i / 1100, rem = i % 1100, n = rem / 11, k = rem % 11;
        float v = (k < 10) ? (tower ? wl1[k * 100 + n] : wv1[k * 100 + n])
                           : (tower ? bl1[n] : bv1[n]);
        st_split(sm, B1OFF + b1_byte(tower ? 112 + n : n, k), v);
    }
    // B2v: permuted rows sigma(c); k<100 = wv2[k][sig], k=100 = bias
    for (int i = tid; i < 56 * 101; i += TPB) {
        int c = i / 101, k = i % 101;
        int sig = (c % 8) / 2 + 8 * (c / 8) + 4 * (c % 2);
        if (sig < 50)
            st_split(sm, B2VOFF + b2_byte(c, k), (k < 100) ? wv2[k * 50 + sig] : bv2[sig]);
    }
    // B2l: row c = 2n+comp
    for (int i = tid; i < 100 * 101; i += TPB) {
        int c = i / 101, k = i % 101;
        float v = (k < 100) ? wl2[(c >> 1) * 200 + k * 2 + (c & 1)] : bl2[c];
        st_split(sm, B2LOFF + b2_byte(c, k), v);
    }
    __syncthreads();

    const int ntiles = (nrows + TILE_M - 1) / TILE_M;
    const int lr0 = w * 16 + g;

    // loop-invariant base pointers; all LDS offsets below are compile-time immediates
    const char* pB1 = sm + g * 64  + q * 16;   // B1: + j*512 (+ 112*64 for loc tower)
    const char* pB2 = sm + g * 448 + q * 16;   // B2: + B2xOFF + j*3584 + ks*64

    for (int tile = blockIdx.x; tile < ntiles; tile += GRIDX) {
        const int grow0 = tile * TILE_M + lr0;
        const int grow1 = grow0 + 8;

        // ---- GEMM1 A-fragments from global s (K=16: s cols 0..9, bias at 10) ----
        uint32_t saH[4], saL[4];
        {
            float2 p0 = make_float2(0.f, 0.f), p1 = p0, e0 = p0, e1 = p0;
            if (grow0 < nrows) p0 = *(const float2*)(s + (size_t)grow0 * 10 + 2 * q);
            if (grow1 < nrows) p1 = *(const float2*)(s + (size_t)grow1 * 10 + 2 * q);
            if (q == 0) {
                if (grow0 < nrows) e0 = *(const float2*)(s + (size_t)grow0 * 10 + 8);
                if (grow1 < nrows) e1 = *(const float2*)(s + (size_t)grow1 * 10 + 8);
            } else if (q == 1) {
                e0.x = 1.0f; e1.x = 1.0f;
            }
            split_pack(p0.x, p0.y, saH[0], saL[0]);
            split_pack(p1.x, p1.y, saH[1], saL[1]);
            split_pack(e0.x, e0.y, saH[2], saL[2]);
            split_pack(e1.x, e1.y, saH[3], saL[3]);
        }

        // ======== GEMM1v with rolling-pair convert (dv live = 2 tiles) ========
        uint32_t vaH[7][4], vaL[7][4];
        #pragma unroll
        for (int jp = 0; jp < 6; jp++) {
            float d0[4] = {0.f, 0.f, 0.f, 0.f}, d1[4] = {0.f, 0.f, 0.f, 0.f};
            {
                uint4 bb = *(const uint4*)(pB1 + (2 * jp) * 512);
                mma16816(d0, saH, bb.x, bb.y);
                mma16816(d0, saH, bb.z, bb.w);
                mma16816(d0, saL, bb.x, bb.y);
            }
            {
                uint4 bb = *(const uint4*)(pB1 + (2 * jp + 1) * 512);
                mma16816(d1, saH, bb.x, bb.y);
                mma16816(d1, saH, bb.z, bb.w);
                mma16816(d1, saL, bb.x, bb.y);
            }
            relu_split(d0[0], d0[1], vaH[jp][0], vaL[jp][0]);
            relu_split(d0[2], d0[3], vaH[jp][1], vaL[jp][1]);
            relu_split(d1[0], d1[1], vaH[jp][2], vaL[jp][2]);
            relu_split(d1[2], d1[3], vaH[jp][3], vaL[jp][3]);
        }
        {
            float d0[4] = {0.f, 0.f, 0.f, 0.f};
            uint4 bb = *(const uint4*)(pB1 + 12 * 512);
            mma16816(d0, saH, bb.x, bb.y);
            mma16816(d0, saH, bb.z, bb.w);
            mma16816(d0, saL, bb.x, bb.y);
            relu_split(d0[0], d0[1], vaH[6][0], vaL[6][0]);
            relu_split(d0[2], d0[3], vaH[6][1], vaL[6][1]);
        }
        if (q == 2) { vaH[6][0] = 0x3F80u; vaL[6][0] = 0u; vaH[6][1] = 0x3F80u; vaL[6][1] = 0u; }
        vaH[6][2] = 0u; vaH[6][3] = 0u; vaL[6][2] = 0u; vaL[6][3] = 0u;

        // ================= GEMM2v: cv = hv x B2v^T =================
        float cv[7][4];
        #pragma unroll
        for (int j = 0; j < 7; j++) { cv[j][0]=0.f; cv[j][1]=0.f; cv[j][2]=0.f; cv[j][3]=0.f; }
        #pragma unroll
        for (int ks = 0; ks < 7; ks++) {
            #pragma unroll
            for (int j = 0; j < 7; j++) {
                uint4 bb = *(const uint4*)(pB2 + B2VOFF + j * 3584 + ks * 64);
                mma16816(cv[j], vaH[ks], bb.x, bb.y);
                mma16816(cv[j], vaH[ks], bb.z, bb.w);
                mma16816(cv[j], vaL[ks], bb.x, bb.y);
            }
        }

        // ======== GEMM1l with rolling-pair convert (dl live = 2 tiles; va dead) ========
        uint32_t laH[7][4], laL[7][4];
        #pragma unroll
        for (int jp = 0; jp < 6; jp++) {
            float d0[4] = {0.f, 0.f, 0.f, 0.f}, d1[4] = {0.f, 0.f, 0.f, 0.f};
            {
                uint4 bb = *(const uint4*)(pB1 + 112 * 64 + (2 * jp) * 512);
                mma16816(d0, saH, bb.x, bb.y);
                mma16816(d0, saH, bb.z, bb.w);
                mma16816(d0, saL, bb.x, bb.y);
            }
            {
                uint4 bb = *(const uint4*)(pB1 + 112 * 64 + (2 * jp + 1) * 512);
                mma16816(d1, saH, bb.x, bb.y);
                mma16816(d1, saH, bb.z, bb.w);
                mma16816(d1, saL, bb.x, bb.y);
            }
            relu_split(d0[0], d0[1], laH[jp][0], laL[jp][0]);
            relu_split(d0[2], d0[3], laH[jp][1], laL[jp][1]);
            relu_split(d1[0], d1[1], laH[jp][2], laL[jp][2]);
            relu_split(d1[2], d1[3], laH[jp][3], laL[jp][3]);
        }
        {
            float d0[4] = {0.f, 0.f, 0.f, 0.f};
            uint4 bb = *(const uint4*)(pB1 + 112 * 64 + 12 * 512);
            mma16816(d0, saH, bb.x, bb.y);
            mma16816(d0, saH, bb.z, bb.w);
            mma16816(d0, saL, bb.x, bb.y);
            relu_split(d0[0], d0[1], laH[6][0], laL[6][0]);
            relu_split(d0[2], d0[3], laH[6][1], laL[6][1]);
        }
        if (q == 2) { laH[6][0] = 0x3F80u; laL[6][0] = 0u; laH[6][1] = 0x3F80u; laL[6][1] = 0u; }
        laH[6][2] = 0u; laH[6][3] = 0u; laL[6][2] = 0u; laL[6][3] = 0u;

        // action rows
        float2 av0 = make_float2(0.f, 0.f), av1 = av0;
        if (grow0 < nrows) av0 = ((const float2*)a)[grow0];
        if (grow1 < nrows) av1 = ((const float2*)a)[grow1];

        // ===== GEMM2l per-j + fused epilogue (lc live = 1 tile) =====
        float ws0 = 0.f, vs0 = 0.f, ws1 = 0.f, vs1 = 0.f;
        #pragma unroll
        for (int j = 0; j < 13; j++) {
            float lc[4] = {0.f, 0.f, 0.f, 0.f};
            #pragma unroll
            for (int ks = 0; ks < 7; ks++) {
                uint4 bb = *(const uint4*)(pB2 + B2LOFF + j * 3584 + ks * 64);
                mma16816(lc, laH[ks], bb.x, bb.y);
                mma16816(lc, laH[ks], bb.z, bb.w);
                mma16816(lc, laL[ks], bb.x, bb.y);
            }
            const bool valid = (4 * j + q) < 50;
            {
                float tx = MAXA * fast_tanh(lc[0]) - av0.x;
                float ty = MAXA * fast_tanh(lc[1]) - av0.y;
                float e = valid ? __expf(-BETA * sqrtf(tx * tx + ty * ty)) : 0.f;
                float c = (j & 1) ? cv[j >> 1][1] : cv[j >> 1][0];
                ws0 += e; vs0 += e * c;
            }
            {
                float tx = MAXA * fast_tanh(lc[2]) - av1.x;
                float ty = MAXA * fast_tanh(lc[3]) - av1.y;
                float e = valid ? __expf(-BETA * sqrtf(tx * tx + ty * ty)) : 0.f;
                float c = (j & 1) ? cv[j >> 1][3] : cv[j >> 1][2];
                ws1 += e; vs1 += e * c;
            }
        }

        ws0 += __shfl_xor_sync(0xffffffffu, ws0, 1);
        vs0 += __shfl_xor_sync(0xffffffffu, vs0, 1);
        ws1 += __shfl_xor_sync(0xffffffffu, ws1, 1);
        vs1 += __shfl_xor_sync(0xffffffffu, vs1, 1);
        ws0 += __shfl_xor_sync(0xffffffffu, ws0, 2);
        vs0 += __shfl_xor_sync(0xffffffffu, vs0, 2);
        ws1 += __shfl_xor_sync(0xffffffffu, ws1, 2);
        vs1 += __shfl_xor_sync(0xffffffffu, vs1, 2);
        if (q == 0) {
            if (grow0 < nrows) out[grow0] = vs0 / ws0;
            if (grow1 < nrows) out[grow1] = vs1 / ws1;
        }
    }
}

extern "C" void kernel_launch(void* const* d_in, const int* in_sizes, int n_in,
                              void* d_out, int out_size)
{
    const float* s   = (const float*)d_in[0];
    const float* a   = (const float*)d_in[1];
    const float* wv1 = (const float*)d_in[2];
    const float* bv1 = (const float*)d_in[3];
    const float* wv2 = (const float*)d_in[4];
    const float* bv2 = (const float*)d_in[5];
    const float* wl1 = (const float*)d_in[6];
    const float* bl1 = (const float*)d_in[7];
    const float* wl2 = (const float*)d_in[8];
    const float* bl2 = (const float*)d_in[9];
    float* out = (float*)d_out;

    int nrows = in_sizes[0] / 10;

    cudaFuncSetAttribute(net_kernel, cudaFuncAttributeMaxDynamicSharedMemorySize, SMEM_BYTES);
    net_kernel<<<GRIDX, TPB, SMEM_BYTES>>>(s, a, wv1, bv1, wv2, bv2,
                                           wl1, bl1, wl2, bl2, out, nrows);
}

// round 15
// speedup vs baseline: 1.0965x; 1.0139x over previous
#include <cuda_runtime.h>
#include <cuda_bf16.h>
#include <cstdint>

#define TPB 512
#define GRIDX 148
#define TILE_M 256
#define BETA 3.0f
#define MAXA 5.0f

// smem: interleaved bf16 hi/lo B layouts, 16B unit = [H0,H1,L0,L1] per (ks,q)
#define B1OFF  0        // 224 rows x 64B   (value rows 0..99, loc rows 112..211)
#define B2VOFF 14336    // 56 rows x 448B
#define B2LOFF 39424    // 104 rows x 448B
#define SMEM_BYTES 86016

// pack two f32 -> bf16x2 (lo=x, hi=y) plus residual word
__device__ __forceinline__ void split_pack(float x, float y, uint32_t& H, uint32_t& L) {
    asm("cvt.rn.bf16x2.f32 %0, %1, %2;" : "=r"(H) : "f"(y), "f"(x));
    float xh = __uint_as_float(H << 16);
    float yh = __uint_as_float(H & 0xFFFF0000u);
    float xr = x - xh, yr = y - yh;
    asm("cvt.rn.bf16x2.f32 %0, %1, %2;" : "=r"(L) : "f"(yr), "f"(xr));
}
__device__ __forceinline__ void relu_split(float x, float y, uint32_t& H, uint32_t& L) {
    split_pack(fmaxf(x, 0.f), fmaxf(y, 0.f), H, L);
}

// staging: write bf16 hi at byte bH, lo at bH+8
__device__ __forceinline__ void st_split(char* sm, int bH, float v) {
    __nv_bfloat16 h = __float2bfloat16(v);
    float r = v - __bfloat162float(h);
    __nv_bfloat16 l = __float2bfloat16(r);
    *(unsigned short*)(sm + bH)     = *(unsigned short*)&h;
    *(unsigned short*)(sm + bH + 8) = *(unsigned short*)&l;
}
// interleaved byte offsets (H slot; L at +8)
__device__ __forceinline__ int b1_byte(int row, int k) {
    int w = k >> 1;
    return row * 64 + (w & 3) * 16 + ((w >> 2) << 2) + ((k & 1) << 1);
}
__device__ __forceinline__ int b2_byte(int row, int k) {
    int w = k >> 1;
    return row * 448 + (w >> 3) * 64 + ((w & 3) << 4) + (((w >> 2) & 1) << 2) + ((k & 1) << 1);
}

// VOLATILE on purpose: prevents ptxas from hoisting/pipelining MMAs, which
// explodes live ranges and spills (R7/R8/R9 regressions all traced to
// non-volatile here). Do not remove volatile. ILP/latency-hiding is created
// in SOURCE order instead (depth-1 rolling LDS prefetch below).
__device__ __forceinline__ void mma16816(float* c, const uint32_t* a, uint32_t b0, uint32_t b1) {
    asm volatile(
        "mma.sync.aligned.m16n8k16.row.col.f32.bf16.bf16.f32 "
        "{%0,%1,%2,%3}, {%4,%5,%6,%7}, {%8,%9}, {%0,%1,%2,%3};"
        : "+f"(c[0]), "+f"(c[1]), "+f"(c[2]), "+f"(c[3])
        : "r"(a[0]), "r"(a[1]), "r"(a[2]), "r"(a[3]), "r"(b0), "r"(b1));
}

__device__ __forceinline__ float fast_tanh(float x) {
    float e = __expf(2.0f * x);
    return 1.0f - __fdividef(2.0f, e + 1.0f);
}

__global__ __launch_bounds__(TPB, 1)
void net_kernel(const float* __restrict__ s,  const float* __restrict__ a,
                const float* __restrict__ wv1, const float* __restrict__ bv1,
                const float* __restrict__ wv2, const float* __restrict__ bv2,
                const float* __restrict__ wl1, const float* __restrict__ bl1,
                const float* __restrict__ wl2, const float* __restrict__ bl2,
                float* __restrict__ out, int nrows)
{
    extern __shared__ __align__(16) char sm[];
    const int tid  = threadIdx.x;
    const int w    = tid >> 5;
    const int lane = tid & 31;
    const int g    = lane >> 2;
    const int q    = lane & 3;

    // zero all smem (covers every pad row/col)
    for (int i = tid * 16; i < SMEM_BYTES; i += TPB * 16)
        *(float4*)(sm + i) = make_float4(0.f, 0.f, 0.f, 0.f);
    __syncthreads();

    // ---- stage weights ----
    // B1: value rows 0..99, loc rows 112..211; k<10 = w1[k][n], k=10 = bias
    for (int i = tid; i < 2200; i += TPB) {
        int tower = i / 1100, rem = i % 1100, n = rem / 11, k = rem % 11;
        float v = (k < 10) ? (tower ? wl1[k * 100 + n] : wv1[k * 100 + n])
                           : (tower ? bl1[n] : bv1[n]);
        st_split(sm, B1OFF + b1_byte(tower ? 112 + n : n, k), v);
    }
    // B2v: permuted rows sigma(c); k<100 = wv2[k][sig], k=100 = bias
    for (int i = tid; i < 56 * 101; i += TPB) {
        int c = i / 101, k = i % 101;
        int sig = (c % 8) / 2 + 8 * (c / 8) + 4 * (c % 2);
        if (sig < 50)
            st_split(sm, B2VOFF + b2_byte(c, k), (k < 100) ? wv2[k * 50 + sig] : bv2[sig]);
    }
    // B2l: row c = 2n+comp
    for (int i = tid; i < 100 * 101; i += TPB) {
        int c = i / 101, k = i % 101;
        float v = (k < 100) ? wl2[(c >> 1) * 200 + k * 2 + (c & 1)] : bl2[c];
        st_split(sm, B2LOFF + b2_byte(c, k), v);
    }
    __syncthreads();

    const int ntiles = (nrows + TILE_M - 1) / TILE_M;
    const int lr0 = w * 16 + g;

    // loop-invariant base pointers; all LDS offsets below are compile-time immediates
    const char* pB1 = sm + g * 64  + q * 16;   // B1: + j*512 (+ 112*64 for loc tower)
    const char* pB2 = sm + g * 448 + q * 16;   // B2: + B2xOFF + j*3584 + ks*64

    for (int tile = blockIdx.x; tile < ntiles; tile += GRIDX) {
        const int grow0 = tile * TILE_M + lr0;
        const int grow1 = grow0 + 8;

        // ---- GEMM1 A-fragments from global s (K=16: s cols 0..9, bias at 10) ----
        uint32_t saH[4], saL[4];
        {
            float2 p0 = make_float2(0.f, 0.f), p1 = p0, e0 = p0, e1 = p0;
            if (grow0 < nrows) p0 = *(const float2*)(s + (size_t)grow0 * 10 + 2 * q);
            if (grow1 < nrows) p1 = *(const float2*)(s + (size_t)grow1 * 10 + 2 * q);
            if (q == 0) {
                if (grow0 < nrows) e0 = *(const float2*)(s + (size_t)grow0 * 10 + 8);
                if (grow1 < nrows) e1 = *(const float2*)(s + (size_t)grow1 * 10 + 8);
            } else if (q == 1) {
                e0.x = 1.0f; e1.x = 1.0f;
            }
            split_pack(p0.x, p0.y, saH[0], saL[0]);
            split_pack(p1.x, p1.y, saH[1], saL[1]);
            split_pack(e0.x, e0.y, saH[2], saL[2]);
            split_pack(e1.x, e1.y, saH[3], saL[3]);
        }

        // ======== GEMM1v with rolling-pair convert (dv live = 2 tiles) ========
        uint32_t vaH[7][4], vaL[7][4];
        #pragma unroll
        for (int jp = 0; jp < 6; jp++) {
            float d0[4] = {0.f, 0.f, 0.f, 0.f}, d1[4] = {0.f, 0.f, 0.f, 0.f};
            {
                uint4 bb = *(const uint4*)(pB1 + (2 * jp) * 512);
                mma16816(d0, saH, bb.x, bb.y);
                mma16816(d0, saH, bb.z, bb.w);
                mma16816(d0, saL, bb.x, bb.y);
            }
            {
                uint4 bb = *(const uint4*)(pB1 + (2 * jp + 1) * 512);
                mma16816(d1, saH, bb.x, bb.y);
                mma16816(d1, saH, bb.z, bb.w);
                mma16816(d1, saL, bb.x, bb.y);
            }
            relu_split(d0[0], d0[1], vaH[jp][0], vaL[jp][0]);
            relu_split(d0[2], d0[3], vaH[jp][1], vaL[jp][1]);
            relu_split(d1[0], d1[1], vaH[jp][2], vaL[jp][2]);
            relu_split(d1[2], d1[3], vaH[jp][3], vaL[jp][3]);
        }
        {
            float d0[4] = {0.f, 0.f, 0.f, 0.f};
            uint4 bb = *(const uint4*)(pB1 + 12 * 512);
            mma16816(d0, saH, bb.x, bb.y);
            mma16816(d0, saH, bb.z, bb.w);
            mma16816(d0, saL, bb.x, bb.y);
            relu_split(d0[0], d0[1], vaH[6][0], vaL[6][0]);
            relu_split(d0[2], d0[3], vaH[6][1], vaL[6][1]);
        }
        if (q == 2) { vaH[6][0] = 0x3F80u; vaL[6][0] = 0u; vaH[6][1] = 0x3F80u; vaL[6][1] = 0u; }
        vaH[6][2] = 0u; vaH[6][3] = 0u; vaL[6][2] = 0u; vaL[6][3] = 0u;

        // ===== GEMM2v: depth-1 rolling LDS prefetch (c = current, n = next) =====
        float cv[7][4];
        #pragma unroll
        for (int j = 0; j < 7; j++) { cv[j][0]=0.f; cv[j][1]=0.f; cv[j][2]=0.f; cv[j][3]=0.f; }
        {
            const char* pv = pB2 + B2VOFF;
            uint4 c = *(const uint4*)(pv);   // (ks=0, j=0)
            #pragma unroll
            for (int ks = 0; ks < 7; ks++) {
                #pragma unroll
                for (int j = 0; j < 7; j++) {
                    const int ni = (j < 6) ? (ks * 64 + (j + 1) * 3584)
                                           : ((ks < 6) ? ((ks + 1) * 64)
                                                       : (6 * 64 + 6 * 3584));  // harmless reload at end
                    uint4 n = *(const uint4*)(pv + ni);
                    mma16816(cv[j], vaH[ks], c.x, c.y);
                    mma16816(cv[j], vaH[ks], c.z, c.w);
                    mma16816(cv[j], vaL[ks], c.x, c.y);
                    c = n;
                }
            }
        }

        // ======== GEMM1l with rolling-pair convert (dl live = 2 tiles; va dead) ========
        uint32_t laH[7][4], laL[7][4];
        #pragma unroll
        for (int jp = 0; jp < 6; jp++) {
            float d0[4] = {0.f, 0.f, 0.f, 0.f}, d1[4] = {0.f, 0.f, 0.f, 0.f};
            {
                uint4 bb = *(const uint4*)(pB1 + 112 * 64 + (2 * jp) * 512);
                mma16816(d0, saH, bb.x, bb.y);
                mma16816(d0, saH, bb.z, bb.w);
                mma16816(d0, saL, bb.x, bb.y);
            }
            {
                uint4 bb = *(const uint4*)(pB1 + 112 * 64 + (2 * jp + 1) * 512);
                mma16816(d1, saH, bb.x, bb.y);
                mma16816(d1, saH, bb.z, bb.w);
                mma16816(d1, saL, bb.x, bb.y);
            }
            relu_split(d0[0], d0[1], laH[jp][0], laL[jp][0]);
            relu_split(d0[2], d0[3], laH[jp][1], laL[jp][1]);
            relu_split(d1[0], d1[1], laH[jp][2], laL[jp][2]);
            relu_split(d1[2], d1[3], laH[jp][3], laL[jp][3]);
        }
        {
            float d0[4] = {0.f, 0.f, 0.f, 0.f};
            uint4 bb = *(const uint4*)(pB1 + 112 * 64 + 12 * 512);
            mma16816(d0, saH, bb.x, bb.y);
            mma16816(d0, saH, bb.z, bb.w);
            mma16816(d0, saL, bb.x, bb.y);
            relu_split(d0[0], d0[1], laH[6][0], laL[6][0]);
            relu_split(d0[2], d0[3], laH[6][1], laL[6][1]);
        }
        if (q == 2) { laH[6][0] = 0x3F80u; laL[6][0] = 0u; laH[6][1] = 0x3F80u; laL[6][1] = 0u; }
        laH[6][2] = 0u; laH[6][3] = 0u; laL[6][2] = 0u; laL[6][3] = 0u;

        // action rows
        float2 av0 = make_float2(0.f, 0.f), av1 = av0;
        if (grow0 < nrows) av0 = ((const float2*)a)[grow0];
        if (grow1 < nrows) av1 = ((const float2*)a)[grow1];

        // ===== GEMM2l per-j + fused epilogue, depth-1 rolling LDS prefetch =====
        float ws0 = 0.f, vs0 = 0.f, ws1 = 0.f, vs1 = 0.f;
        {
            const char* pl = pB2 + B2LOFF;
            uint4 c = *(const uint4*)(pl);   // (j=0, ks=0)
            #pragma unroll
            for (int j = 0; j < 13; j++) {
                float lc[4] = {0.f, 0.f, 0.f, 0.f};
                #pragma unroll
                for (int ks = 0; ks < 7; ks++) {
                    const int ni = (ks < 6) ? (j * 3584 + (ks + 1) * 64)
                                            : ((j < 12) ? ((j + 1) * 3584)
                                                        : (12 * 3584 + 6 * 64));  // harmless reload at end
                    uint4 n = *(const uint4*)(pl + ni);
                    mma16816(lc, laH[ks], c.x, c.y);
                    mma16816(lc, laH[ks], c.z, c.w);
                    mma16816(lc, laL[ks], c.x, c.y);
                    c = n;
                }
                const bool valid = (4 * j + q) < 50;
                {
                    float tx = MAXA * fast_tanh(lc[0]) - av0.x;
                    float ty = MAXA * fast_tanh(lc[1]) - av0.y;
                    float e = valid ? __expf(-BETA * sqrtf(tx * tx + ty * ty)) : 0.f;
                    float cc = (j & 1) ? cv[j >> 1][1] : cv[j >> 1][0];
                    ws0 += e; vs0 += e * cc;
                }
                {
                    float tx = MAXA * fast_tanh(lc[2]) - av1.x;
                    float ty = MAXA * fast_tanh(lc[3]) - av1.y;
                    float e = valid ? __expf(-BETA * sqrtf(tx * tx + ty * ty)) : 0.f;
                    float cc = (j & 1) ? cv[j >> 1][3] : cv[j >> 1][2];
                    ws1 += e; vs1 += e * cc;
                }
            }
        }

        ws0 += __shfl_xor_sync(0xffffffffu, ws0, 1);
        vs0 += __shfl_xor_sync(0xffffffffu, vs0, 1);
        ws1 += __shfl_xor_sync(0xffffffffu, ws1, 1);
        vs1 += __shfl_xor_sync(0xffffffffu, vs1, 1);
        ws0 += __shfl_xor_sync(0xffffffffu, ws0, 2);
        vs0 += __shfl_xor_sync(0xffffffffu, vs0, 2);
        ws1 += __shfl_xor_sync(0xffffffffu, ws1, 2);
        vs1 += __shfl_xor_sync(0xffffffffu, vs1, 2);
        if (q == 0) {
            if (grow0 < nrows) out[grow0] = vs0 / ws0;
            if (grow1 < nrows) out[grow1] = vs1 / ws1;
        }
    }
}

extern "C" void kernel_launch(void* const* d_in, const int* in_sizes, int n_in,
                              void* d_out, int out_size)
{
    const float* s   = (const float*)d_in[0];
    const float* a   = (const float*)d_in[1];
    const float* wv1 = (const float*)d_in[2];
    const float* bv1 = (const float*)d_in[3];
    const float* wv2 = (const float*)d_in[4];
    const float* bv2 = (const float*)d_in[5];
    const float* wl1 = (const float*)d_in[6];
    const float* bl1 = (const float*)d_in[7];
    const float* wl2 = (const float*)d_in[8];
    const float* bl2 = (const float*)d_in[9];
    float* out = (float*)d_out;

    int nrows = in_sizes[0] / 10;

    cudaFuncSetAttribute(net_kernel, cudaFuncAttributeMaxDynamicSharedMemorySize, SMEM_BYTES);
    net_kernel<<<GRIDX, TPB, SMEM_BYTES>>>(s, a, wv1, bv1, wv2, bv2,
                                           wl1, bl1, wl2, bl2, out, nrows);
}